// round 15
// baseline (speedup 1.0000x reference)
#include <cuda_runtime.h>
#include <cuda_fp16.h>
#include <cstdint>

#define HD   128
#define RR   8
#define NMAX 50000
#define EMAX 500000
#define NK   (NMAX * RR)        // 400000 bins
#define KTOT (HD + RR * HD)     // 1152
#define NCHUNK 36               // 1152 / 32
#define AST  40                 // smem row stride (fp16 elems): 32 + 8 pad
#define BELEMS (128 * KTOT)     // 147456 weight elems per layer

#define ABYTES (128 * AST * 2)          // 10240 bytes per A stage
#define STAGEB (2 * ABYTES)             // A + B per stage = 20480
#define NSTAGE 4
#define SM_WC   (NSTAGE * STAGEB)       // 81920: Wc (128 floats)
#define SM_RED  (SM_WC + 512)           // reduce buffer (128*2 floats)
#define SMEMSZ  (SM_RED + 1024)         // 83456 bytes

// ---------------- scratch (static device globals; no allocation) ----------------
__device__ __half g_aggh[(size_t)NMAX * RR * HD];   // [N,8,128] fp16, mean applied
__device__ int   g_cnt[NK];
__device__ int   g_off[NK];
__device__ int   g_cur[NK];
__device__ int   g_bsum[512];
__device__ int   g_esrc[EMAX];
__device__ __half g_xh[(size_t)NMAX * HD];
__device__ __half g_h1[(size_t)NMAX * HD];
__device__ __half g_B1[128 * KTOT];                 // B^T fp16: [n][k]
__device__ __half g_B2[128 * KTOT];

// ---------------- mma.sync / ldmatrix / cp.async helpers (base PTX, sm_80+) -----
__device__ __forceinline__ uint32_t smem_u32(const void* p) {
    return (uint32_t)__cvta_generic_to_shared(p);
}
__device__ __forceinline__ void ldsm_x4(uint32_t* r, uint32_t addr) {
    asm volatile("ldmatrix.sync.aligned.m8n8.x4.shared.b16 {%0,%1,%2,%3}, [%4];"
                 : "=r"(r[0]), "=r"(r[1]), "=r"(r[2]), "=r"(r[3]) : "r"(addr));
}
__device__ __forceinline__ void mma16816(float* d, const uint32_t* a, const uint32_t* b) {
    asm volatile(
        "mma.sync.aligned.m16n8k16.row.col.f32.f16.f16.f32 "
        "{%0,%1,%2,%3}, {%4,%5,%6,%7}, {%8,%9}, {%0,%1,%2,%3};"
        : "+f"(d[0]), "+f"(d[1]), "+f"(d[2]), "+f"(d[3])
        : "r"(a[0]), "r"(a[1]), "r"(a[2]), "r"(a[3]), "r"(b[0]), "r"(b[1]));
}
__device__ __forceinline__ void cp_async16(uint32_t smem_dst, const void* gptr) {
    asm volatile("cp.async.cg.shared.global [%0], [%1], 16;"
                 :: "r"(smem_dst), "l"(gptr));
}
__device__ __forceinline__ void cp_commit() { asm volatile("cp.async.commit_group;"); }
__device__ __forceinline__ void cp_wait0()  { asm volatile("cp.async.wait_group 0;"); }
__device__ __forceinline__ void cp_wait1()  { asm volatile("cp.async.wait_group 1;"); }
__device__ __forceinline__ void cp_wait2()  { asm volatile("cp.async.wait_group 2;"); }

// ---------------- fused prep: B1/B2 fp16, xh fp16, zero cnt ----------------
__global__ void prep_all(const float* __restrict__ r1, const float* __restrict__ W1,
                         const float* __restrict__ r2, const float* __restrict__ W2,
                         const float* __restrict__ x,
                         __half* B1, __half* B2, __half* xh,
                         int* cnt, int M) {
    int t = blockIdx.x * blockDim.x + threadIdx.x;
    int nx4 = M * HD / 4;
    if (t < 2 * BELEMS) {
        const float* root = (t < BELEMS) ? r1 : r2;
        const float* W    = (t < BELEMS) ? W1 : W2;
        __half* B         = (t < BELEMS) ? B1 : B2;
        int i = (t < BELEMS) ? t : t - BELEMS;
        int n = i / KTOT, k = i % KTOT;
        float v = (k < HD) ? root[k * HD + n] : W[(size_t)(k - HD) * HD + n];
        B[i] = __float2half(v);
    } else if (t < 2 * BELEMS + nx4) {
        int i = (t - 2 * BELEMS) * 4;
        float4 v = *(const float4*)(x + i);
        __half2 a = __floats2half2_rn(v.x, v.y), b = __floats2half2_rn(v.z, v.w);
        *(uint2*)(xh + i) = make_uint2(*(uint32_t*)&a, *(uint32_t*)&b);
    } else if (t < 2 * BELEMS + nx4 + NK / 4) {
        int i = t - 2 * BELEMS - nx4;
        ((int4*)cnt)[i] = make_int4(0, 0, 0, 0);
    }
}

// ---------------- CSR build: count -> scan (2 kernels) -> place ----------------
__global__ void count_kernel(const int* __restrict__ dst, const int* __restrict__ et,
                             int* cnt, int E) {
    int e = blockIdx.x * blockDim.x + threadIdx.x;
    if (e < E) atomicAdd(&cnt[dst[e] * RR + et[e]], 1);
}

// per-block sums (raw, not prefixed)
__global__ void scan1_kernel(const int* __restrict__ cnt, int* bsum, int nk) {
    __shared__ int sh[256];
    int b = blockIdx.x, t = threadIdx.x;
    int base = b * 1024 + t * 4;
    int s = 0;
    if (base + 3 < nk) {
        int4 v = *(const int4*)(cnt + base);
        s = v.x + v.y + v.z + v.w;
    } else {
        for (int j = 0; j < 4; j++) if (base + j < nk) s += cnt[base + j];
    }
    sh[t] = s; __syncthreads();
    for (int o = 128; o; o >>= 1) { if (t < o) sh[t] += sh[t + o]; __syncthreads(); }
    if (t == 0) bsum[b] = sh[0];
}

// local scan + self-computed block prefix (sums bsum[0..b-1] cooperatively)
__global__ void scan3_kernel(const int* __restrict__ cnt, const int* __restrict__ bsum,
                             int* off, int* cur, int nk) {
    __shared__ int sh[256];
    __shared__ int spre[256];
    int b = blockIdx.x, t = threadIdx.x;

    // block prefix: sum of bsum[0..b-1]
    int pacc = 0;
    for (int i = t; i < b; i += 256) pacc += bsum[i];
    spre[t] = pacc; __syncthreads();
    for (int o = 128; o; o >>= 1) { if (t < o) spre[t] += spre[t + o]; __syncthreads(); }
    int bpref = spre[0];

    int base = b * 1024 + t * 4;
    int v[4] = {0, 0, 0, 0};
    if (base + 3 < nk) {
        int4 q = *(const int4*)(cnt + base);
        v[0] = q.x; v[1] = q.y; v[2] = q.z; v[3] = q.w;
    } else {
        for (int j = 0; j < 4; j++) if (base + j < nk) v[j] = cnt[base + j];
    }
    int ts = v[0] + v[1] + v[2] + v[3];
    sh[t] = ts; __syncthreads();
    for (int o = 1; o < 256; o <<= 1) {
        int add = (t >= o) ? sh[t - o] : 0;
        __syncthreads();
        sh[t] += add;
        __syncthreads();
    }
    int excl = sh[t] - ts + bpref;
    int o0 = excl, o1 = o0 + v[0], o2 = o1 + v[1], o3 = o2 + v[2];
    if (base + 3 < nk) {
        *(int4*)(off + base) = make_int4(o0, o1, o2, o3);
        *(int4*)(cur + base) = make_int4(o0, o1, o2, o3);
    } else {
        int oo[4] = {o0, o1, o2, o3};
        for (int j = 0; j < 4; j++)
            if (base + j < nk) { off[base + j] = oo[j]; cur[base + j] = oo[j]; }
    }
}

__global__ void place_kernel(const int* __restrict__ src, const int* __restrict__ dst,
                             const int* __restrict__ et, int* cur, int* esrc, int E) {
    int e = blockIdx.x * blockDim.x + threadIdx.x;
    if (e >= E) return;
    int key = dst[e] * RR + et[e];
    int pos = atomicAdd(&cur[key], 1);
    esrc[pos] = src[e];
}

// ---------------- aggregation: warp per node, merged edge walk ----------------
// Node w's edges are contiguous [off[w*8], cur[w*8+7]) sorted by rel.
// Single accumulator, emitted at each rel boundary; prefetch streams across
// segment boundaries (condition on node end e[7], not segment end).
__global__ void agg_kernel(const __half* __restrict__ feat, const int* __restrict__ esrc,
                           const int* __restrict__ off, const int* __restrict__ cur,
                           __half* __restrict__ agg, int M) {
    int w = (blockIdx.x * blockDim.x + threadIdx.x) >> 5;
    int lane = threadIdx.x & 31;
    if (w >= M) return;
    int key0 = w * RR;
    int ev = (lane < RR) ? cur[key0 + lane] : 0;
    int s0 = off[key0];
    int e[8];
#pragma unroll
    for (int r = 0; r < 8; r++) e[r] = __shfl_sync(0xffffffffu, ev, r);
    const int eend = e[7];

    const uint2* fp = (const uint2*)feat;   // 32 uint2 per row
    int eidx = s0;
    uint2 u = make_uint2(0u, 0u);
    if (eidx < eend) {
        int sc = esrc[eidx];
        u = fp[(size_t)sc * 32 + lane];
    }

    size_t ob = (size_t)w * (RR * HD) + lane * 4;
    int st = s0;
#pragma unroll
    for (int rel = 0; rel < 8; rel++) {
        int en = e[rel];
        float a0 = 0.f, a1 = 0.f, a2 = 0.f, a3 = 0.f;
        for (; eidx < en; eidx++) {
            uint2 cu = u;
            if (eidx + 1 < eend) {
                int sn = esrc[eidx + 1];
                u = fp[(size_t)sn * 32 + lane];
            }
            float2 f0 = __half22float2(*(const __half2*)&cu.x);
            float2 f1 = __half22float2(*(const __half2*)&cu.y);
            a0 += f0.x; a1 += f0.y; a2 += f1.x; a3 += f1.y;
        }
        int c = en - st;
        uint2 o = make_uint2(0u, 0u);
        if (c > 0) {
            float s = 1.0f / (float)c;
            __half2 h0 = __floats2half2_rn(a0 * s, a1 * s);
            __half2 h1 = __floats2half2_rn(a2 * s, a3 * s);
            o = make_uint2(*(uint32_t*)&h0, *(uint32_t*)&h1);
        }
        *(uint2*)(agg + ob + rel * HD) = o;
        st = en;
    }
}

// ---------------- fp16 mma.sync GEMM, 4-stage cp.async pipeline ----------------
// relu( [Xh | Aggh] @ B + bias ) -> Hout fp16, OR (Wc != null) -> out[row] = dot+bc
__global__ __launch_bounds__(256, 2) void rgcn_mma(
    const __half* __restrict__ Xh, const __half* __restrict__ Aggh,
    const __half* __restrict__ B,
    const float* __restrict__ bias, __half* __restrict__ Hout, int M,
    const float* __restrict__ Wc, const float* __restrict__ bc,
    float* __restrict__ out) {

    extern __shared__ char smem[];
    const uint32_t sb = smem_u32(smem);
    float* Wcs = (float*)(smem + SM_WC);
    float* red = (float*)(smem + SM_RED);

    const int tid = threadIdx.x;
    const int wid = tid >> 5;
    const int lane = tid & 31;
    const int brow = blockIdx.x * 128;
    const bool fused = (Wc != nullptr);

    if (fused && tid < 128) Wcs[tid] = Wc[tid];

    const int warp_m = wid & 3, warp_n = wid >> 2;
    const int mr0 = warp_m * 32, nc0 = warp_n * 64;

    const int alr = lane & 15, alc = (lane >> 4) << 3;
    const uint32_t aA0 = sb + (mr0 + alr) * (AST * 2) + alc * 2;
    const uint32_t aA1 = sb + (mr0 + 16 + alr) * (AST * 2) + alc * 2;
    const int blr = (lane & 7) + ((lane >> 4) << 3);
    const int blc = ((lane >> 3) & 1) << 3;
    uint32_t aBx[4];
#pragma unroll
    for (int j = 0; j < 4; j++)
        aBx[j] = sb + ABYTES + (nc0 + blr + j * 16) * (AST * 2) + blc * 2;

    float acc[2][8][4];
#pragma unroll
    for (int i = 0; i < 2; i++)
#pragma unroll
        for (int j = 0; j < 8; j++)
#pragma unroll
            for (int q = 0; q < 4; q++) acc[i][j][q] = 0.f;

    const int arow = tid >> 1;
    const int aks  = (tid & 1) << 4;
    int g = brow + arow;
    if (g >= M) g = M - 1;

    auto cpA = [&](int c, int st) {
        const __half* s = (c < 4)
            ? Xh + (size_t)g * HD + c * 32 + aks
            : Aggh + (size_t)g * (RR * HD) + (c - 4) * 32 + aks;
        uint32_t d = sb + st * STAGEB + arow * (AST * 2) + aks * 2;
        cp_async16(d, s);
        cp_async16(d + 16, s + 8);
    };
    auto cpB = [&](int c, int st) {
        const __half* b = B + (size_t)arow * KTOT + c * 32 + aks;
        uint32_t d = sb + st * STAGEB + ABYTES + arow * (AST * 2) + aks * 2;
        cp_async16(d, b);
        cp_async16(d + 16, b + 8);
    };

    cpA(0, 0); cpB(0, 0); cp_commit();
    cpA(1, 1); cpB(1, 1); cp_commit();
    cpA(2, 2); cpB(2, 2); cp_commit();

    for (int c = 0; c < NCHUNK; c++) {
        if (c + 2 < NCHUNK)      cp_wait2();
        else if (c + 1 < NCHUNK) cp_wait1();
        else                     cp_wait0();
        __syncthreads();

        if (c + 3 < NCHUNK) {
            cpA(c + 3, (c + 3) & 3);
            cpB(c + 3, (c + 3) & 3);
            cp_commit();
        }

        const uint32_t bo = (uint32_t)(c & 3) * STAGEB;
#pragma unroll
        for (int k16 = 0; k16 < 2; k16++) {
            const uint32_t kb = bo + k16 * 32;
            uint32_t Af[2][4];
            ldsm_x4(Af[0], aA0 + kb);
            ldsm_x4(Af[1], aA1 + kb);
            uint32_t Bf[8][2];
#pragma unroll
            for (int j = 0; j < 4; j++) {
                uint32_t t[4];
                ldsm_x4(t, aBx[j] + kb);
                Bf[2 * j][0] = t[0]; Bf[2 * j][1] = t[1];
                Bf[2 * j + 1][0] = t[2]; Bf[2 * j + 1][1] = t[3];
            }
#pragma unroll
            for (int mf = 0; mf < 2; mf++)
#pragma unroll
                for (int nf = 0; nf < 8; nf++) mma16816(acc[mf][nf], Af[mf], Bf[nf]);
        }
    }

    const int er = lane >> 2, ec = (lane & 3) * 2;
    float2 bv[8];
#pragma unroll
    for (int nf = 0; nf < 8; nf++)
        bv[nf] = *(const float2*)(bias + nc0 + nf * 8 + ec);

    if (!fused) {
#pragma unroll
        for (int mf = 0; mf < 2; mf++) {
#pragma unroll
            for (int half = 0; half < 2; half++) {
                int gr = brow + mr0 + mf * 16 + half * 8 + er;
                if (gr < M) {
                    __half* op = Hout + (size_t)gr * HD + nc0 + ec;
#pragma unroll
                    for (int nf = 0; nf < 8; nf++) {
                        float ox = fmaxf(acc[mf][nf][half * 2]     + bv[nf].x, 0.f);
                        float oy = fmaxf(acc[mf][nf][half * 2 + 1] + bv[nf].y, 0.f);
                        *(__half2*)(op + nf * 8) = __floats2half2_rn(ox, oy);
                    }
                }
            }
        }
    } else {
        __syncthreads();
#pragma unroll
        for (int mf = 0; mf < 2; mf++) {
#pragma unroll
            for (int half = 0; half < 2; half++) {
                int rl = mr0 + mf * 16 + half * 8 + er;
                float s = 0.f;
#pragma unroll
                for (int nf = 0; nf < 8; nf++) {
                    float ox = fmaxf(acc[mf][nf][half * 2]     + bv[nf].x, 0.f);
                    float oy = fmaxf(acc[mf][nf][half * 2 + 1] + bv[nf].y, 0.f);
                    s += ox * Wcs[nc0 + nf * 8 + ec] + oy * Wcs[nc0 + nf * 8 + ec + 1];
                }
                s += __shfl_xor_sync(0xffffffffu, s, 1);
                s += __shfl_xor_sync(0xffffffffu, s, 2);
                if ((lane & 3) == 0) red[rl * 2 + warp_n] = s;
            }
        }
        __syncthreads();
        if (tid < 128) {
            int gr = brow + tid;
            if (gr < M) out[gr] = red[tid * 2] + red[tid * 2 + 1] + bc[0];
        }
    }
}

// ---------------- launch ----------------
extern "C" void kernel_launch(void* const* d_in, const int* in_sizes, int n_in,
                              void* d_out, int out_size) {
    const float* x  = (const float*)d_in[0];
    const int*   ei = (const int*)d_in[1];
    const int*   et = (const int*)d_in[2];
    const float* W1 = (const float*)d_in[3];
    const float* r1 = (const float*)d_in[4];
    const float* b1 = (const float*)d_in[5];
    const float* W2 = (const float*)d_in[6];
    const float* r2 = (const float*)d_in[7];
    const float* b2 = (const float*)d_in[8];
    const float* Wc = (const float*)d_in[9];
    const float* bc = (const float*)d_in[10];

    int M = in_sizes[0] / HD;    // 50000
    int E = in_sizes[1] / 2;     // 500000
    const int* src = ei;
    const int* dst = ei + E;

    __half *aggh, *xh, *h1;
    int *cnt, *off, *cur, *bsum, *esrc;
    __half *B1, *B2;
    cudaGetSymbolAddress((void**)&aggh, g_aggh);
    cudaGetSymbolAddress((void**)&cnt, g_cnt);
    cudaGetSymbolAddress((void**)&off, g_off);
    cudaGetSymbolAddress((void**)&cur, g_cur);
    cudaGetSymbolAddress((void**)&bsum, g_bsum);
    cudaGetSymbolAddress((void**)&esrc, g_esrc);
    cudaGetSymbolAddress((void**)&xh, g_xh);
    cudaGetSymbolAddress((void**)&h1, g_h1);
    cudaGetSymbolAddress((void**)&B1, g_B1);
    cudaGetSymbolAddress((void**)&B2, g_B2);

    cudaFuncSetAttribute(rgcn_mma, cudaFuncAttributeMaxDynamicSharedMemorySize, SMEMSZ);

    int nk = M * RR;
    int nb = (nk + 1023) / 1024;                  // 391
    int mblocks = (M + 127) / 128;                // 391
    int eblocks = (E + 255) / 256;
    int ablocks = (M * 32 + 255) / 256;           // 1 warp per node
    int ptotal = 2 * BELEMS + M * HD / 4 + nk / 4;
    int pblocks = (ptotal + 255) / 256;

    // fused prep: weights fp16, x fp16, zero cnt
    prep_all<<<pblocks, 256>>>(r1, W1, r2, W2, x, B1, B2, xh, cnt, M);

    // ---- CSR build (shared by both layers) ----
    count_kernel<<<eblocks, 256>>>(dst, et, cnt, E);
    scan1_kernel<<<nb, 256>>>(cnt, bsum, nk);
    scan3_kernel<<<nb, 256>>>(cnt, bsum, off, cur, nk);
    place_kernel<<<eblocks, 256>>>(src, dst, et, cur, esrc, E);

    // ---- layer 1 ----
    agg_kernel<<<ablocks, 256>>>(xh, esrc, off, cur, aggh, M);
    rgcn_mma<<<mblocks, 256, SMEMSZ>>>(xh, aggh, B1, b1, h1, M,
                                       nullptr, nullptr, nullptr);

    // ---- layer 2 + fused classifier ----
    agg_kernel<<<ablocks, 256>>>(h1, esrc, off, cur, aggh, M);
    rgcn_mma<<<mblocks, 256, SMEMSZ>>>(h1, aggh, B2, b2, nullptr, M,
                                       Wc, bc, (float*)d_out);
}

// round 16
// speedup vs baseline: 1.0425x; 1.0425x over previous
#include <cuda_runtime.h>
#include <cuda_fp16.h>
#include <cstdint>

#define HD   128
#define RR   8
#define NMAX 50000
#define EMAX 500000
#define NK   (NMAX * RR)        // 400000 bins
#define KTOT (HD + RR * HD)     // 1152
#define NCHUNK 36               // 1152 / 32
#define AST  40                 // smem row stride (fp16 elems): 32 + 8 pad
#define BELEMS (128 * KTOT)     // 147456 weight elems per layer

#define ABYTES (128 * AST * 2)          // 10240 bytes per A stage
#define STAGEB (2 * ABYTES)             // A + B per stage = 20480
#define NSTAGE 4
#define SM_WC   (NSTAGE * STAGEB)       // 81920: Wc (128 floats)
#define SM_RED  (SM_WC + 512)           // reduce buffer (128*2 floats)
#define SMEMSZ  (SM_RED + 1024)         // 83456 bytes

// ---------------- scratch (static device globals; no allocation) ----------------
__device__ __half g_aggh[(size_t)NMAX * RR * HD];   // [N,8,128] fp16, mean applied
__device__ int   g_cnt[NK];
__device__ int   g_off[NK];
__device__ int   g_cur[NK];
__device__ int   g_bsum[512];
__device__ int   g_esrc[EMAX];
__device__ __half g_xh[(size_t)NMAX * HD];
__device__ __half g_h1[(size_t)NMAX * HD];
__device__ __half g_B1[128 * KTOT];                 // B^T fp16: [n][k]
__device__ __half g_B2[128 * KTOT];

// ---------------- mma.sync / ldmatrix / cp.async helpers (base PTX, sm_80+) -----
__device__ __forceinline__ uint32_t smem_u32(const void* p) {
    return (uint32_t)__cvta_generic_to_shared(p);
}
__device__ __forceinline__ void ldsm_x4(uint32_t* r, uint32_t addr) {
    asm volatile("ldmatrix.sync.aligned.m8n8.x4.shared.b16 {%0,%1,%2,%3}, [%4];"
                 : "=r"(r[0]), "=r"(r[1]), "=r"(r[2]), "=r"(r[3]) : "r"(addr));
}
__device__ __forceinline__ void mma16816(float* d, const uint32_t* a, const uint32_t* b) {
    asm volatile(
        "mma.sync.aligned.m16n8k16.row.col.f32.f16.f16.f32 "
        "{%0,%1,%2,%3}, {%4,%5,%6,%7}, {%8,%9}, {%0,%1,%2,%3};"
        : "+f"(d[0]), "+f"(d[1]), "+f"(d[2]), "+f"(d[3])
        : "r"(a[0]), "r"(a[1]), "r"(a[2]), "r"(a[3]), "r"(b[0]), "r"(b[1]));
}
__device__ __forceinline__ void cp_async16(uint32_t smem_dst, const void* gptr) {
    asm volatile("cp.async.cg.shared.global [%0], [%1], 16;"
                 :: "r"(smem_dst), "l"(gptr));
}
__device__ __forceinline__ void cp_commit() { asm volatile("cp.async.commit_group;"); }
__device__ __forceinline__ void cp_wait0()  { asm volatile("cp.async.wait_group 0;"); }
__device__ __forceinline__ void cp_wait1()  { asm volatile("cp.async.wait_group 1;"); }
__device__ __forceinline__ void cp_wait2()  { asm volatile("cp.async.wait_group 2;"); }

// ---------------- zero cnt ----------------
__global__ void zerocnt_kernel(int4* cnt) {
    int t = blockIdx.x * blockDim.x + threadIdx.x;
    if (t < NK / 4) cnt[t] = make_int4(0, 0, 0, 0);
}

// ---------------- fused prep + count: weights fp16, xh fp16, edge histogram -----
__global__ void prep_count(const float* __restrict__ r1, const float* __restrict__ W1,
                           const float* __restrict__ r2, const float* __restrict__ W2,
                           const float* __restrict__ x,
                           __half* B1, __half* B2, __half* xh,
                           const int* __restrict__ dst, const int* __restrict__ et,
                           int* cnt, int M, int E) {
    int t = blockIdx.x * blockDim.x + threadIdx.x;
    int nx4 = M * HD / 4;
    if (t < 2 * BELEMS) {
        const float* root = (t < BELEMS) ? r1 : r2;
        const float* W    = (t < BELEMS) ? W1 : W2;
        __half* B         = (t < BELEMS) ? B1 : B2;
        int i = (t < BELEMS) ? t : t - BELEMS;
        int n = i / KTOT, k = i % KTOT;
        float v = (k < HD) ? root[k * HD + n] : W[(size_t)(k - HD) * HD + n];
        B[i] = __float2half(v);
    } else if (t < 2 * BELEMS + nx4) {
        int i = (t - 2 * BELEMS) * 4;
        float4 v = *(const float4*)(x + i);
        __half2 a = __floats2half2_rn(v.x, v.y), b = __floats2half2_rn(v.z, v.w);
        *(uint2*)(xh + i) = make_uint2(*(uint32_t*)&a, *(uint32_t*)&b);
    } else if (t < 2 * BELEMS + nx4 + E) {
        int e = t - 2 * BELEMS - nx4;
        atomicAdd(&cnt[dst[e] * RR + et[e]], 1);
    }
}

// ---------------- CSR scan (2 kernels) -> place ----------------
// per-block sums (raw, not prefixed)
__global__ void scan1_kernel(const int* __restrict__ cnt, int* bsum, int nk) {
    __shared__ int sh[256];
    int b = blockIdx.x, t = threadIdx.x;
    int base = b * 1024 + t * 4;
    int s = 0;
    if (base + 3 < nk) {
        int4 v = *(const int4*)(cnt + base);
        s = v.x + v.y + v.z + v.w;
    } else {
        for (int j = 0; j < 4; j++) if (base + j < nk) s += cnt[base + j];
    }
    sh[t] = s; __syncthreads();
    for (int o = 128; o; o >>= 1) { if (t < o) sh[t] += sh[t + o]; __syncthreads(); }
    if (t == 0) bsum[b] = sh[0];
}

// local scan + self-computed block prefix (sums bsum[0..b-1] cooperatively)
__global__ void scan3_kernel(const int* __restrict__ cnt, const int* __restrict__ bsum,
                             int* off, int* cur, int nk) {
    __shared__ int sh[256];
    __shared__ int spre[256];
    int b = blockIdx.x, t = threadIdx.x;

    int pacc = 0;
    for (int i = t; i < b; i += 256) pacc += bsum[i];
    spre[t] = pacc; __syncthreads();
    for (int o = 128; o; o >>= 1) { if (t < o) spre[t] += spre[t + o]; __syncthreads(); }
    int bpref = spre[0];

    int base = b * 1024 + t * 4;
    int v[4] = {0, 0, 0, 0};
    if (base + 3 < nk) {
        int4 q = *(const int4*)(cnt + base);
        v[0] = q.x; v[1] = q.y; v[2] = q.z; v[3] = q.w;
    } else {
        for (int j = 0; j < 4; j++) if (base + j < nk) v[j] = cnt[base + j];
    }
    int ts = v[0] + v[1] + v[2] + v[3];
    sh[t] = ts; __syncthreads();
    for (int o = 1; o < 256; o <<= 1) {
        int add = (t >= o) ? sh[t - o] : 0;
        __syncthreads();
        sh[t] += add;
        __syncthreads();
    }
    int excl = sh[t] - ts + bpref;
    int o0 = excl, o1 = o0 + v[0], o2 = o1 + v[1], o3 = o2 + v[2];
    if (base + 3 < nk) {
        *(int4*)(off + base) = make_int4(o0, o1, o2, o3);
        *(int4*)(cur + base) = make_int4(o0, o1, o2, o3);
    } else {
        int oo[4] = {o0, o1, o2, o3};
        for (int j = 0; j < 4; j++)
            if (base + j < nk) { off[base + j] = oo[j]; cur[base + j] = oo[j]; }
    }
}

__global__ void place_kernel(const int* __restrict__ src, const int* __restrict__ dst,
                             const int* __restrict__ et, int* cur, int* esrc, int E) {
    int e = blockIdx.x * blockDim.x + threadIdx.x;
    if (e >= E) return;
    int key = dst[e] * RR + et[e];
    int pos = atomicAdd(&cur[key], 1);
    esrc[pos] = src[e];
}

// ---------------- aggregation: warp per dst node (R12-proven) ----------------
__global__ void agg_kernel(const __half* __restrict__ feat, const int* __restrict__ esrc,
                           const int* __restrict__ off, const int* __restrict__ cur,
                           __half* __restrict__ agg, int M) {
    int w = (blockIdx.x * blockDim.x + threadIdx.x) >> 5;
    int lane = threadIdx.x & 31;
    if (w >= M) return;
#pragma unroll
    for (int rel = 0; rel < RR; rel++) {
        int key = w * RR + rel;
        int s0 = off[key], s1 = cur[key];
        size_t ob = (size_t)w * (RR * HD) + rel * HD + lane * 4;
        if (s0 >= s1) {
            *(uint2*)(agg + ob) = make_uint2(0u, 0u);
            continue;
        }
        float a0 = 0.f, a1 = 0.f, a2 = 0.f, a3 = 0.f;
        int snext = esrc[s0];
        for (int e = s0; e < s1; e++) {
            int sc = snext;
            if (e + 1 < s1) snext = esrc[e + 1];
            uint2 u = *(const uint2*)(feat + (size_t)sc * HD + lane * 4);
            float2 f0 = __half22float2(*(const __half2*)&u.x);
            float2 f1 = __half22float2(*(const __half2*)&u.y);
            a0 += f0.x; a1 += f0.y; a2 += f1.x; a3 += f1.y;
        }
        float s = 1.0f / (float)(s1 - s0);
        __half2 h0 = __floats2half2_rn(a0 * s, a1 * s);
        __half2 h1 = __floats2half2_rn(a2 * s, a3 * s);
        *(uint2*)(agg + ob) = make_uint2(*(uint32_t*)&h0, *(uint32_t*)&h1);
    }
}

// ---------------- fp16 mma.sync GEMM, 4-stage cp.async pipeline ----------------
// relu( [Xh | Aggh] @ B + bias ) -> Hout fp16, OR (Wc != null) -> out[row] = dot+bc
__global__ __launch_bounds__(256, 2) void rgcn_mma(
    const __half* __restrict__ Xh, const __half* __restrict__ Aggh,
    const __half* __restrict__ B,
    const float* __restrict__ bias, __half* __restrict__ Hout, int M,
    const float* __restrict__ Wc, const float* __restrict__ bc,
    float* __restrict__ out) {

    extern __shared__ char smem[];
    const uint32_t sb = smem_u32(smem);
    float* Wcs = (float*)(smem + SM_WC);
    float* red = (float*)(smem + SM_RED);

    const int tid = threadIdx.x;
    const int wid = tid >> 5;
    const int lane = tid & 31;
    const int brow = blockIdx.x * 128;
    const bool fused = (Wc != nullptr);

    if (fused && tid < 128) Wcs[tid] = Wc[tid];

    const int warp_m = wid & 3, warp_n = wid >> 2;
    const int mr0 = warp_m * 32, nc0 = warp_n * 64;

    const int alr = lane & 15, alc = (lane >> 4) << 3;
    const uint32_t aA0 = sb + (mr0 + alr) * (AST * 2) + alc * 2;
    const uint32_t aA1 = sb + (mr0 + 16 + alr) * (AST * 2) + alc * 2;
    const int blr = (lane & 7) + ((lane >> 4) << 3);
    const int blc = ((lane >> 3) & 1) << 3;
    uint32_t aBx[4];
#pragma unroll
    for (int j = 0; j < 4; j++)
        aBx[j] = sb + ABYTES + (nc0 + blr + j * 16) * (AST * 2) + blc * 2;

    float acc[2][8][4];
#pragma unroll
    for (int i = 0; i < 2; i++)
#pragma unroll
        for (int j = 0; j < 8; j++)
#pragma unroll
            for (int q = 0; q < 4; q++) acc[i][j][q] = 0.f;

    const int arow = tid >> 1;
    const int aks  = (tid & 1) << 4;
    int g = brow + arow;
    if (g >= M) g = M - 1;

    auto cpA = [&](int c, int st) {
        const __half* s = (c < 4)
            ? Xh + (size_t)g * HD + c * 32 + aks
            : Aggh + (size_t)g * (RR * HD) + (c - 4) * 32 + aks;
        uint32_t d = sb + st * STAGEB + arow * (AST * 2) + aks * 2;
        cp_async16(d, s);
        cp_async16(d + 16, s + 8);
    };
    auto cpB = [&](int c, int st) {
        const __half* b = B + (size_t)arow * KTOT + c * 32 + aks;
        uint32_t d = sb + st * STAGEB + ABYTES + arow * (AST * 2) + aks * 2;
        cp_async16(d, b);
        cp_async16(d + 16, b + 8);
    };

    cpA(0, 0); cpB(0, 0); cp_commit();
    cpA(1, 1); cpB(1, 1); cp_commit();
    cpA(2, 2); cpB(2, 2); cp_commit();

    for (int c = 0; c < NCHUNK; c++) {
        if (c + 2 < NCHUNK)      cp_wait2();
        else if (c + 1 < NCHUNK) cp_wait1();
        else                     cp_wait0();
        __syncthreads();

        if (c + 3 < NCHUNK) {
            cpA(c + 3, (c + 3) & 3);
            cpB(c + 3, (c + 3) & 3);
            cp_commit();
        }

        const uint32_t bo = (uint32_t)(c & 3) * STAGEB;
#pragma unroll
        for (int k16 = 0; k16 < 2; k16++) {
            const uint32_t kb = bo + k16 * 32;
            uint32_t Af[2][4];
            ldsm_x4(Af[0], aA0 + kb);
            ldsm_x4(Af[1], aA1 + kb);
            uint32_t Bf[8][2];
#pragma unroll
            for (int j = 0; j < 4; j++) {
                uint32_t t[4];
                ldsm_x4(t, aBx[j] + kb);
                Bf[2 * j][0] = t[0]; Bf[2 * j][1] = t[1];
                Bf[2 * j + 1][0] = t[2]; Bf[2 * j + 1][1] = t[3];
            }
#pragma unroll
            for (int mf = 0; mf < 2; mf++)
#pragma unroll
                for (int nf = 0; nf < 8; nf++) mma16816(acc[mf][nf], Af[mf], Bf[nf]);
        }
    }

    const int er = lane >> 2, ec = (lane & 3) * 2;
    float2 bv[8];
#pragma unroll
    for (int nf = 0; nf < 8; nf++)
        bv[nf] = *(const float2*)(bias + nc0 + nf * 8 + ec);

    if (!fused) {
#pragma unroll
        for (int mf = 0; mf < 2; mf++) {
#pragma unroll
            for (int half = 0; half < 2; half++) {
                int gr = brow + mr0 + mf * 16 + half * 8 + er;
                if (gr < M) {
                    __half* op = Hout + (size_t)gr * HD + nc0 + ec;
#pragma unroll
                    for (int nf = 0; nf < 8; nf++) {
                        float ox = fmaxf(acc[mf][nf][half * 2]     + bv[nf].x, 0.f);
                        float oy = fmaxf(acc[mf][nf][half * 2 + 1] + bv[nf].y, 0.f);
                        *(__half2*)(op + nf * 8) = __floats2half2_rn(ox, oy);
                    }
                }
            }
        }
    } else {
        __syncthreads();
#pragma unroll
        for (int mf = 0; mf < 2; mf++) {
#pragma unroll
            for (int half = 0; half < 2; half++) {
                int rl = mr0 + mf * 16 + half * 8 + er;
                float s = 0.f;
#pragma unroll
                for (int nf = 0; nf < 8; nf++) {
                    float ox = fmaxf(acc[mf][nf][half * 2]     + bv[nf].x, 0.f);
                    float oy = fmaxf(acc[mf][nf][half * 2 + 1] + bv[nf].y, 0.f);
                    s += ox * Wcs[nc0 + nf * 8 + ec] + oy * Wcs[nc0 + nf * 8 + ec + 1];
                }
                s += __shfl_xor_sync(0xffffffffu, s, 1);
                s += __shfl_xor_sync(0xffffffffu, s, 2);
                if ((lane & 3) == 0) red[rl * 2 + warp_n] = s;
            }
        }
        __syncthreads();
        if (tid < 128) {
            int gr = brow + tid;
            if (gr < M) out[gr] = red[tid * 2] + red[tid * 2 + 1] + bc[0];
        }
    }
}

// ---------------- launch ----------------
extern "C" void kernel_launch(void* const* d_in, const int* in_sizes, int n_in,
                              void* d_out, int out_size) {
    const float* x  = (const float*)d_in[0];
    const int*   ei = (const int*)d_in[1];
    const int*   et = (const int*)d_in[2];
    const float* W1 = (const float*)d_in[3];
    const float* r1 = (const float*)d_in[4];
    const float* b1 = (const float*)d_in[5];
    const float* W2 = (const float*)d_in[6];
    const float* r2 = (const float*)d_in[7];
    const float* b2 = (const float*)d_in[8];
    const float* Wc = (const float*)d_in[9];
    const float* bc = (const float*)d_in[10];

    int M = in_sizes[0] / HD;    // 50000
    int E = in_sizes[1] / 2;     // 500000
    const int* src = ei;
    const int* dst = ei + E;

    __half *aggh, *xh, *h1;
    int *cnt, *off, *cur, *bsum, *esrc;
    __half *B1, *B2;
    cudaGetSymbolAddress((void**)&aggh, g_aggh);
    cudaGetSymbolAddress((void**)&cnt, g_cnt);
    cudaGetSymbolAddress((void**)&off, g_off);
    cudaGetSymbolAddress((void**)&cur, g_cur);
    cudaGetSymbolAddress((void**)&bsum, g_bsum);
    cudaGetSymbolAddress((void**)&esrc, g_esrc);
    cudaGetSymbolAddress((void**)&xh, g_xh);
    cudaGetSymbolAddress((void**)&h1, g_h1);
    cudaGetSymbolAddress((void**)&B1, g_B1);
    cudaGetSymbolAddress((void**)&B2, g_B2);

    cudaFuncSetAttribute(rgcn_mma, cudaFuncAttributeMaxDynamicSharedMemorySize, SMEMSZ);

    int nk = M * RR;
    int nb = (nk + 1023) / 1024;                  // 391
    int mblocks = (M + 127) / 128;                // 391
    int eblocks = (E + 255) / 256;
    int ablocks = (M * 32 + 255) / 256;
    int pctotal = 2 * BELEMS + M * HD / 4 + E;
    int pcblocks = (pctotal + 255) / 256;
    int zblocks = (NK / 4 + 255) / 256;

    // ---- CSR build + prep (count hides prep work) ----
    zerocnt_kernel<<<zblocks, 256>>>((int4*)cnt);
    prep_count<<<pcblocks, 256>>>(r1, W1, r2, W2, x, B1, B2, xh, dst, et, cnt, M, E);
    scan1_kernel<<<nb, 256>>>(cnt, bsum, nk);
    scan3_kernel<<<nb, 256>>>(cnt, bsum, off, cur, nk);
    place_kernel<<<eblocks, 256>>>(src, dst, et, cur, esrc, E);

    // ---- layer 1 ----
    agg_kernel<<<ablocks, 256>>>(xh, esrc, off, cur, aggh, M);
    rgcn_mma<<<mblocks, 256, SMEMSZ>>>(xh, aggh, B1, b1, h1, M,
                                       nullptr, nullptr, nullptr);

    // ---- layer 2 + fused classifier ----
    agg_kernel<<<ablocks, 256>>>(h1, esrc, off, cur, aggh, M);
    rgcn_mma<<<mblocks, 256, SMEMSZ>>>(h1, aggh, B2, b2, nullptr, M,
                                       Wc, bc, (float*)d_out);
}

// round 17
// speedup vs baseline: 1.0529x; 1.0100x over previous
#include <cuda_runtime.h>
#include <cuda_fp16.h>
#include <cstdint>

#define HD   128
#define RR   8
#define NMAX 50000
#define EMAX 500000
#define NK   (NMAX * RR)        // 400000 bins
#define KTOT (HD + RR * HD)     // 1152
#define NCHUNK 36               // 1152 / 32
#define AST  40                 // smem row stride (fp16 elems): 32 + 8 pad
#define BELEMS (128 * KTOT)     // 147456 weight elems per layer

#define ABYTES (128 * AST * 2)          // 10240 bytes per A stage
#define STAGEB (2 * ABYTES)             // A + B per stage = 20480
#define NSTAGE 4
#define SM_WC   (NSTAGE * STAGEB)       // 81920: Wc (128 floats)
#define SM_RED  (SM_WC + 512)           // reduce buffer (128*2 floats)
#define SMEMSZ  (SM_RED + 1024)         // 83456 bytes

// ---------------- scratch (static device globals; no allocation) ----------------
__device__ __half g_aggh[(size_t)NMAX * RR * HD];   // [N,8,128] fp16, mean applied
__device__ int   g_cnt[NK];
__device__ int   g_off[NK];
__device__ int   g_cur[NK];
__device__ int   g_bsum[512];
__device__ int   g_esrc[EMAX];
__device__ __half g_xh[(size_t)NMAX * HD];
__device__ __half g_h1[(size_t)NMAX * HD];
__device__ __half g_B1[128 * KTOT];                 // B^T fp16: [n][k]
__device__ __half g_B2[128 * KTOT];

// ---------------- mma.sync / ldmatrix / cp.async helpers (base PTX, sm_80+) -----
__device__ __forceinline__ uint32_t smem_u32(const void* p) {
    return (uint32_t)__cvta_generic_to_shared(p);
}
__device__ __forceinline__ void ldsm_x4(uint32_t* r, uint32_t addr) {
    asm volatile("ldmatrix.sync.aligned.m8n8.x4.shared.b16 {%0,%1,%2,%3}, [%4];"
                 : "=r"(r[0]), "=r"(r[1]), "=r"(r[2]), "=r"(r[3]) : "r"(addr));
}
__device__ __forceinline__ void mma16816(float* d, const uint32_t* a, const uint32_t* b) {
    asm volatile(
        "mma.sync.aligned.m16n8k16.row.col.f32.f16.f16.f32 "
        "{%0,%1,%2,%3}, {%4,%5,%6,%7}, {%8,%9}, {%0,%1,%2,%3};"
        : "+f"(d[0]), "+f"(d[1]), "+f"(d[2]), "+f"(d[3])
        : "r"(a[0]), "r"(a[1]), "r"(a[2]), "r"(a[3]), "r"(b[0]), "r"(b[1]));
}
__device__ __forceinline__ void cp_async16(uint32_t smem_dst, const void* gptr) {
    asm volatile("cp.async.cg.shared.global [%0], [%1], 16;"
                 :: "r"(smem_dst), "l"(gptr));
}
__device__ __forceinline__ void cp_commit() { asm volatile("cp.async.commit_group;"); }
__device__ __forceinline__ void cp_wait0()  { asm volatile("cp.async.wait_group 0;"); }
__device__ __forceinline__ void cp_wait1()  { asm volatile("cp.async.wait_group 1;"); }
__device__ __forceinline__ void cp_wait2()  { asm volatile("cp.async.wait_group 2;"); }

// ---------------- zero cnt ----------------
__global__ void zerocnt_kernel(int4* cnt) {
    int t = blockIdx.x * blockDim.x + threadIdx.x;
    if (t < NK / 4) cnt[t] = make_int4(0, 0, 0, 0);
}

// ---------------- fused prep + count: weights fp16, xh fp16, edge histogram -----
__global__ void prep_count(const float* __restrict__ r1, const float* __restrict__ W1,
                           const float* __restrict__ r2, const float* __restrict__ W2,
                           const float* __restrict__ x,
                           __half* B1, __half* B2, __half* xh,
                           const int* __restrict__ dst, const int* __restrict__ et,
                           int* cnt, int M, int E) {
    int t = blockIdx.x * blockDim.x + threadIdx.x;
    int nx4 = M * HD / 4;
    if (t < 2 * BELEMS) {
        const float* root = (t < BELEMS) ? r1 : r2;
        const float* W    = (t < BELEMS) ? W1 : W2;
        __half* B         = (t < BELEMS) ? B1 : B2;
        int i = (t < BELEMS) ? t : t - BELEMS;
        int n = i / KTOT, k = i % KTOT;
        float v = (k < HD) ? root[k * HD + n] : W[(size_t)(k - HD) * HD + n];
        B[i] = __float2half(v);
    } else if (t < 2 * BELEMS + nx4) {
        int i = (t - 2 * BELEMS) * 4;
        float4 v = *(const float4*)(x + i);
        __half2 a = __floats2half2_rn(v.x, v.y), b = __floats2half2_rn(v.z, v.w);
        *(uint2*)(xh + i) = make_uint2(*(uint32_t*)&a, *(uint32_t*)&b);
    } else if (t < 2 * BELEMS + nx4 + E) {
        int e = t - 2 * BELEMS - nx4;
        atomicAdd(&cnt[dst[e] * RR + et[e]], 1);
    }
}

// ---------------- CSR scan (2 kernels) -> place ----------------
// per-block sums (raw, not prefixed)
__global__ void scan1_kernel(const int* __restrict__ cnt, int* bsum, int nk) {
    __shared__ int sh[256];
    int b = blockIdx.x, t = threadIdx.x;
    int base = b * 1024 + t * 4;
    int s = 0;
    if (base + 3 < nk) {
        int4 v = *(const int4*)(cnt + base);
        s = v.x + v.y + v.z + v.w;
    } else {
        for (int j = 0; j < 4; j++) if (base + j < nk) s += cnt[base + j];
    }
    sh[t] = s; __syncthreads();
    for (int o = 128; o; o >>= 1) { if (t < o) sh[t] += sh[t + o]; __syncthreads(); }
    if (t == 0) bsum[b] = sh[0];
}

// local scan + self-computed block prefix (sums bsum[0..b-1] cooperatively)
__global__ void scan3_kernel(const int* __restrict__ cnt, const int* __restrict__ bsum,
                             int* off, int* cur, int nk) {
    __shared__ int sh[256];
    __shared__ int spre[256];
    int b = blockIdx.x, t = threadIdx.x;

    int pacc = 0;
    for (int i = t; i < b; i += 256) pacc += __ldg(&bsum[i]);
    spre[t] = pacc; __syncthreads();
    for (int o = 128; o; o >>= 1) { if (t < o) spre[t] += spre[t + o]; __syncthreads(); }
    int bpref = spre[0];

    int base = b * 1024 + t * 4;
    int v[4] = {0, 0, 0, 0};
    if (base + 3 < nk) {
        int4 q = *(const int4*)(cnt + base);
        v[0] = q.x; v[1] = q.y; v[2] = q.z; v[3] = q.w;
    } else {
        for (int j = 0; j < 4; j++) if (base + j < nk) v[j] = cnt[base + j];
    }
    int ts = v[0] + v[1] + v[2] + v[3];
    sh[t] = ts; __syncthreads();
    for (int o = 1; o < 256; o <<= 1) {
        int add = (t >= o) ? sh[t - o] : 0;
        __syncthreads();
        sh[t] += add;
        __syncthreads();
    }
    int excl = sh[t] - ts + bpref;
    int o0 = excl, o1 = o0 + v[0], o2 = o1 + v[1], o3 = o2 + v[2];
    if (base + 3 < nk) {
        *(int4*)(off + base) = make_int4(o0, o1, o2, o3);
        *(int4*)(cur + base) = make_int4(o0, o1, o2, o3);
    } else {
        int oo[4] = {o0, o1, o2, o3};
        for (int j = 0; j < 4; j++)
            if (base + j < nk) { off[base + j] = oo[j]; cur[base + j] = oo[j]; }
    }
}

// 2 edges per thread: doubled atomic MLP, half the blocks
__global__ void place_kernel(const int* __restrict__ src, const int* __restrict__ dst,
                             const int* __restrict__ et, int* cur, int* esrc, int E) {
    int t = blockIdx.x * blockDim.x + threadIdx.x;
    int e0 = t * 2;
    if (e0 >= E) return;
    int d0 = dst[e0], r0 = et[e0], s0 = src[e0];
    if (e0 + 1 < E) {
        int d1 = dst[e0 + 1], r1 = et[e0 + 1], s1 = src[e0 + 1];
        int p0 = atomicAdd(&cur[d0 * RR + r0], 1);
        int p1 = atomicAdd(&cur[d1 * RR + r1], 1);
        esrc[p0] = s0;
        esrc[p1] = s1;
    } else {
        int p0 = atomicAdd(&cur[d0 * RR + r0], 1);
        esrc[p0] = s0;
    }
}

// ---------------- aggregation: warp per dst node (R12-proven) ----------------
__global__ void agg_kernel(const __half* __restrict__ feat, const int* __restrict__ esrc,
                           const int* __restrict__ off, const int* __restrict__ cur,
                           __half* __restrict__ agg, int M) {
    int w = (blockIdx.x * blockDim.x + threadIdx.x) >> 5;
    int lane = threadIdx.x & 31;
    if (w >= M) return;
#pragma unroll
    for (int rel = 0; rel < RR; rel++) {
        int key = w * RR + rel;
        int s0 = __ldg(&off[key]), s1 = __ldg(&cur[key]);
        size_t ob = (size_t)w * (RR * HD) + rel * HD + lane * 4;
        if (s0 >= s1) {
            *(uint2*)(agg + ob) = make_uint2(0u, 0u);
            continue;
        }
        float a0 = 0.f, a1 = 0.f, a2 = 0.f, a3 = 0.f;
        int snext = __ldg(&esrc[s0]);
        for (int e = s0; e < s1; e++) {
            int sc = snext;
            if (e + 1 < s1) snext = __ldg(&esrc[e + 1]);
            uint2 u = *(const uint2*)(feat + (size_t)sc * HD + lane * 4);
            float2 f0 = __half22float2(*(const __half2*)&u.x);
            float2 f1 = __half22float2(*(const __half2*)&u.y);
            a0 += f0.x; a1 += f0.y; a2 += f1.x; a3 += f1.y;
        }
        float s = 1.0f / (float)(s1 - s0);
        __half2 h0 = __floats2half2_rn(a0 * s, a1 * s);
        __half2 h1 = __floats2half2_rn(a2 * s, a3 * s);
        *(uint2*)(agg + ob) = make_uint2(*(uint32_t*)&h0, *(uint32_t*)&h1);
    }
}

// ---------------- fp16 mma.sync GEMM, 4-stage cp.async pipeline ----------------
// relu( [Xh | Aggh] @ B + bias ) -> Hout fp16, OR (Wc != null) -> out[row] = dot+bc
__global__ __launch_bounds__(256, 2) void rgcn_mma(
    const __half* __restrict__ Xh, const __half* __restrict__ Aggh,
    const __half* __restrict__ B,
    const float* __restrict__ bias, __half* __restrict__ Hout, int M,
    const float* __restrict__ Wc, const float* __restrict__ bc,
    float* __restrict__ out) {

    extern __shared__ char smem[];
    const uint32_t sb = smem_u32(smem);
    float* Wcs = (float*)(smem + SM_WC);
    float* red = (float*)(smem + SM_RED);

    const int tid = threadIdx.x;
    const int wid = tid >> 5;
    const int lane = tid & 31;
    const int brow = blockIdx.x * 128;
    const bool fused = (Wc != nullptr);

    if (fused && tid < 128) Wcs[tid] = Wc[tid];

    const int warp_m = wid & 3, warp_n = wid >> 2;
    const int mr0 = warp_m * 32, nc0 = warp_n * 64;

    const int alr = lane & 15, alc = (lane >> 4) << 3;
    const uint32_t aA0 = sb + (mr0 + alr) * (AST * 2) + alc * 2;
    const uint32_t aA1 = sb + (mr0 + 16 + alr) * (AST * 2) + alc * 2;
    const int blr = (lane & 7) + ((lane >> 4) << 3);
    const int blc = ((lane >> 3) & 1) << 3;
    uint32_t aBx[4];
#pragma unroll
    for (int j = 0; j < 4; j++)
        aBx[j] = sb + ABYTES + (nc0 + blr + j * 16) * (AST * 2) + blc * 2;

    float acc[2][8][4];
#pragma unroll
    for (int i = 0; i < 2; i++)
#pragma unroll
        for (int j = 0; j < 8; j++)
#pragma unroll
            for (int q = 0; q < 4; q++) acc[i][j][q] = 0.f;

    const int arow = tid >> 1;
    const int aks  = (tid & 1) << 4;
    int g = brow + arow;
    if (g >= M) g = M - 1;

    auto cpA = [&](int c, int st) {
        const __half* s = (c < 4)
            ? Xh + (size_t)g * HD + c * 32 + aks
            : Aggh + (size_t)g * (RR * HD) + (c - 4) * 32 + aks;
        uint32_t d = sb + st * STAGEB + arow * (AST * 2) + aks * 2;
        cp_async16(d, s);
        cp_async16(d + 16, s + 8);
    };
    auto cpB = [&](int c, int st) {
        const __half* b = B + (size_t)arow * KTOT + c * 32 + aks;
        uint32_t d = sb + st * STAGEB + ABYTES + arow * (AST * 2) + aks * 2;
        cp_async16(d, b);
        cp_async16(d + 16, b + 8);
    };

    cpA(0, 0); cpB(0, 0); cp_commit();
    cpA(1, 1); cpB(1, 1); cp_commit();
    cpA(2, 2); cpB(2, 2); cp_commit();

    for (int c = 0; c < NCHUNK; c++) {
        if (c + 2 < NCHUNK)      cp_wait2();
        else if (c + 1 < NCHUNK) cp_wait1();
        else                     cp_wait0();
        __syncthreads();

        if (c + 3 < NCHUNK) {
            cpA(c + 3, (c + 3) & 3);
            cpB(c + 3, (c + 3) & 3);
            cp_commit();
        }

        const uint32_t bo = (uint32_t)(c & 3) * STAGEB;
#pragma unroll
        for (int k16 = 0; k16 < 2; k16++) {
            const uint32_t kb = bo + k16 * 32;
            uint32_t Af[2][4];
            ldsm_x4(Af[0], aA0 + kb);
            ldsm_x4(Af[1], aA1 + kb);
            uint32_t Bf[8][2];
#pragma unroll
            for (int j = 0; j < 4; j++) {
                uint32_t t[4];
                ldsm_x4(t, aBx[j] + kb);
                Bf[2 * j][0] = t[0]; Bf[2 * j][1] = t[1];
                Bf[2 * j + 1][0] = t[2]; Bf[2 * j + 1][1] = t[3];
            }
#pragma unroll
            for (int mf = 0; mf < 2; mf++)
#pragma unroll
                for (int nf = 0; nf < 8; nf++) mma16816(acc[mf][nf], Af[mf], Bf[nf]);
        }
    }

    const int er = lane >> 2, ec = (lane & 3) * 2;
    float2 bv[8];
#pragma unroll
    for (int nf = 0; nf < 8; nf++)
        bv[nf] = *(const float2*)(bias + nc0 + nf * 8 + ec);

    if (!fused) {
#pragma unroll
        for (int mf = 0; mf < 2; mf++) {
#pragma unroll
            for (int half = 0; half < 2; half++) {
                int gr = brow + mr0 + mf * 16 + half * 8 + er;
                if (gr < M) {
                    __half* op = Hout + (size_t)gr * HD + nc0 + ec;
#pragma unroll
                    for (int nf = 0; nf < 8; nf++) {
                        float ox = fmaxf(acc[mf][nf][half * 2]     + bv[nf].x, 0.f);
                        float oy = fmaxf(acc[mf][nf][half * 2 + 1] + bv[nf].y, 0.f);
                        *(__half2*)(op + nf * 8) = __floats2half2_rn(ox, oy);
                    }
                }
            }
        }
    } else {
        __syncthreads();
#pragma unroll
        for (int mf = 0; mf < 2; mf++) {
#pragma unroll
            for (int half = 0; half < 2; half++) {
                int rl = mr0 + mf * 16 + half * 8 + er;
                float s = 0.f;
#pragma unroll
                for (int nf = 0; nf < 8; nf++) {
                    float ox = fmaxf(acc[mf][nf][half * 2]     + bv[nf].x, 0.f);
                    float oy = fmaxf(acc[mf][nf][half * 2 + 1] + bv[nf].y, 0.f);
                    s += ox * Wcs[nc0 + nf * 8 + ec] + oy * Wcs[nc0 + nf * 8 + ec + 1];
                }
                s += __shfl_xor_sync(0xffffffffu, s, 1);
                s += __shfl_xor_sync(0xffffffffu, s, 2);
                if ((lane & 3) == 0) red[rl * 2 + warp_n] = s;
            }
        }
        __syncthreads();
        if (tid < 128) {
            int gr = brow + tid;
            if (gr < M) out[gr] = red[tid * 2] + red[tid * 2 + 1] + bc[0];
        }
    }
}

// ---------------- launch ----------------
extern "C" void kernel_launch(void* const* d_in, const int* in_sizes, int n_in,
                              void* d_out, int out_size) {
    const float* x  = (const float*)d_in[0];
    const int*   ei = (const int*)d_in[1];
    const int*   et = (const int*)d_in[2];
    const float* W1 = (const float*)d_in[3];
    const float* r1 = (const float*)d_in[4];
    const float* b1 = (const float*)d_in[5];
    const float* W2 = (const float*)d_in[6];
    const float* r2 = (const float*)d_in[7];
    const float* b2 = (const float*)d_in[8];
    const float* Wc = (const float*)d_in[9];
    const float* bc = (const float*)d_in[10];

    int M = in_sizes[0] / HD;    // 50000
    int E = in_sizes[1] / 2;     // 500000
    const int* src = ei;
    const int* dst = ei + E;

    __half *aggh, *xh, *h1;
    int *cnt, *off, *cur, *bsum, *esrc;
    __half *B1, *B2;
    cudaGetSymbolAddress((void**)&aggh, g_aggh);
    cudaGetSymbolAddress((void**)&cnt, g_cnt);
    cudaGetSymbolAddress((void**)&off, g_off);
    cudaGetSymbolAddress((void**)&cur, g_cur);
    cudaGetSymbolAddress((void**)&bsum, g_bsum);
    cudaGetSymbolAddress((void**)&esrc, g_esrc);
    cudaGetSymbolAddress((void**)&xh, g_xh);
    cudaGetSymbolAddress((void**)&h1, g_h1);
    cudaGetSymbolAddress((void**)&B1, g_B1);
    cudaGetSymbolAddress((void**)&B2, g_B2);

    cudaFuncSetAttribute(rgcn_mma, cudaFuncAttributeMaxDynamicSharedMemorySize, SMEMSZ);

    int nk = M * RR;
    int nb = (nk + 1023) / 1024;                  // 391
    int mblocks = (M + 127) / 128;                // 391
    int pblocks2 = ((E + 1) / 2 + 255) / 256;     // place: 2 edges/thread
    int ablocks = (M * 32 + 255) / 256;
    int pctotal = 2 * BELEMS + M * HD / 4 + E;
    int pcblocks = (pctotal + 255) / 256;
    int zblocks = (NK / 4 + 255) / 256;

    // ---- CSR build + prep (count hides prep work) ----
    zerocnt_kernel<<<zblocks, 256>>>((int4*)cnt);
    prep_count<<<pcblocks, 256>>>(r1, W1, r2, W2, x, B1, B2, xh, dst, et, cnt, M, E);
    scan1_kernel<<<nb, 256>>>(cnt, bsum, nk);
    scan3_kernel<<<nb, 256>>>(cnt, bsum, off, cur, nk);
    place_kernel<<<pblocks2, 256>>>(src, dst, et, cur, esrc, E);

    // ---- layer 1 ----
    agg_kernel<<<ablocks, 256>>>(xh, esrc, off, cur, aggh, M);
    rgcn_mma<<<mblocks, 256, SMEMSZ>>>(xh, aggh, B1, b1, h1, M,
                                       nullptr, nullptr, nullptr);

    // ---- layer 2 + fused classifier ----
    agg_kernel<<<ablocks, 256>>>(h1, esrc, off, cur, aggh, M);
    rgcn_mma<<<mblocks, 256, SMEMSZ>>>(h1, aggh, B2, b2, nullptr, M,
                                       Wc, bc, (float*)d_out);
}